// round 13
// baseline (speedup 1.0000x reference)
#include <cuda_runtime.h>
#include <cuda_fp16.h>
#include <cstdint>
#include <math.h>

#define BB 8
#define RR 256
#define DD 128
#define NROW (BB*RR)
#define NEG 0.1f
#define SXH 136            // X row stride (halves): 272B = 17x16B (odd) -> ldmatrix conflict-free
#define SWH 136            // Wt row stride (halves): same property
#define JH 128             // j rows per CTA (half tile)

// Persistent scratch (no allocations allowed)
__device__ float  g_h[NROW*DD];
__device__ float  g_ti[NROW*DD];
__device__ __half g_tjh[NROW*DD];    // tj stored fp16 (edge consumes via cp.async)
__device__ float  g_mp2[2*NROW*DD];  // per-jhalf partial mpre

__device__ __forceinline__ float lrelu(float x){ return x > 0.f ? x : NEG*x; }

__device__ __forceinline__ void pair_bar(int id){
    asm volatile("bar.sync %0, %1;" :: "r"(id), "r"(64) : "memory");
}
__device__ __forceinline__ uint32_t smem_u32(const void* p){
    return (uint32_t)__cvta_generic_to_shared(p);
}
__device__ __forceinline__ void ldsm_x4(uint32_t& r0, uint32_t& r1, uint32_t& r2, uint32_t& r3,
                                        uint32_t addr){
    asm volatile("ldmatrix.sync.aligned.m8n8.x4.shared.b16 {%0,%1,%2,%3}, [%4];"
        : "=r"(r0), "=r"(r1), "=r"(r2), "=r"(r3) : "r"(addr));
}

// ---------------------------------------------------------------------------
// F1: fused embed + titj.  8 rows/block, 256 threads = 128 cols x 2 halves.
// ---------------------------------------------------------------------------
__global__ void __launch_bounds__(256)
k_embed_titj(const float* __restrict__ fres, const float* __restrict__ Wemb,
             const float* __restrict__ We1, const float* __restrict__ be1)
{
    __shared__ float sF[8][20];
    __shared__ float sH[8][DD];
    const int r0 = blockIdx.x*8;
    const int t = threadIdx.x, c = t & 127, half = t >> 7;

    for (int idx = t; idx < 8*20; idx += 256)
        sF[idx/20][idx%20] = fres[(size_t)(r0 + idx/20)*20 + idx%20];
    __syncthreads();

    {   // embed: 4 rows per thread
        float a[4] = {0,0,0,0};
        #pragma unroll
        for (int k = 0; k < 20; k++){
            float wv = Wemb[k*DD + c];
            #pragma unroll
            for (int i = 0; i < 4; i++) a[i] += sF[half*4+i][k]*wv;
        }
        #pragma unroll
        for (int i = 0; i < 4; i++){
            float hv = lrelu(a[i]);
            sH[half*4+i][c] = hv;
            g_h[(size_t)(r0+half*4+i)*DD + c] = hv;
        }
    }
    __syncthreads();

    {   // titj: 8 rows per thread; half 0 -> ti, half 1 -> tj(fp16)
        const float* W = We1 + (size_t)half*DD*DD;
        float a[8] = {0,0,0,0,0,0,0,0};
        #pragma unroll 4
        for (int k = 0; k < DD; k++){
            float wv = W[(size_t)k*DD + c];
            #pragma unroll
            for (int r = 0; r < 8; r++) a[r] += sH[r][k]*wv;
        }
        if (half == 0){
            const float be = be1[c];
            #pragma unroll
            for (int r = 0; r < 8; r++) g_ti[(size_t)(r0+r)*DD + c] = a[r] + be;
        } else {
            #pragma unroll
            for (int r = 0; r < 8; r++)
                g_tjh[(size_t)(r0+r)*DD + c] = __float2half_rn(a[r]);
        }
    }
}

// ---------------------------------------------------------------------------
// F2: fused node update (u1,u2) + titj for the next iteration.  8 rows/block.
// ---------------------------------------------------------------------------
__global__ void __launch_bounds__(256)
k_node_titj(const float* __restrict__ Wh1, const float* __restrict__ bh1,
            const float* __restrict__ Wh2, const float* __restrict__ bh2,
            const float* __restrict__ We1, const float* __restrict__ be1)
{
    __shared__ float sHM[8][2*DD];   // [h | mpre]
    __shared__ float sU[8][DD];
    __shared__ float sHN[8][DD];
    const int r0 = blockIdx.x*8;
    const int t = threadIdx.x, c = t & 127, half = t >> 7;

    for (int idx = t; idx < 8*DD; idx += 256){
        int r = idx >> 7, cc = idx & 127;
        sHM[r][cc]      = g_h[(size_t)(r0+r)*DD + cc];
        sHM[r][DD + cc] = g_mp2[(size_t)(r0+r)*DD + cc]
                        + g_mp2[(size_t)(NROW + r0+r)*DD + cc];
    }
    __syncthreads();

    {   // u1: 4 rows per thread, K=256
        float a[4] = {0,0,0,0};
        #pragma unroll 4
        for (int k = 0; k < 2*DD; k++){
            float wv = Wh1[(size_t)k*DD + c];
            #pragma unroll
            for (int i = 0; i < 4; i++) a[i] += sHM[half*4+i][k]*wv;
        }
        const float b1 = bh1[c];
        #pragma unroll
        for (int i = 0; i < 4; i++) sU[half*4+i][c] = lrelu(a[i] + b1);
    }
    __syncthreads();

    {   // u2 + residual: 4 rows per thread
        float a[4] = {0,0,0,0};
        #pragma unroll 4
        for (int k = 0; k < DD; k++){
            float wv = Wh2[(size_t)k*DD + c];
            #pragma unroll
            for (int i = 0; i < 4; i++) a[i] += sU[half*4+i][k]*wv;
        }
        const float b2 = bh2[c];
        #pragma unroll
        for (int i = 0; i < 4; i++){
            float hn = a[i] + b2 + sHM[half*4+i][c];
            sHN[half*4+i][c] = hn;
            g_h[(size_t)(r0+half*4+i)*DD + c] = hn;
        }
    }
    __syncthreads();

    {   // titj on updated h: 8 rows per thread
        const float* W = We1 + (size_t)half*DD*DD;
        float a[8] = {0,0,0,0,0,0,0,0};
        #pragma unroll 4
        for (int k = 0; k < DD; k++){
            float wv = W[(size_t)k*DD + c];
            #pragma unroll
            for (int r = 0; r < 8; r++) a[r] += sHN[r][k]*wv;
        }
        if (half == 0){
            const float be = be1[c];
            #pragma unroll
            for (int r = 0; r < 8; r++) g_ti[(size_t)(r0+r)*DD + c] = a[r] + be;
        } else {
            #pragma unroll
            for (int r = 0; r < 8; r++)
                g_tjh[(size_t)(r0+r)*DD + c] = __float2half_rn(a[r]);
        }
    }
}

// ---------------------------------------------------------------------------
// F3: final node update -> out.  8 rows/block.
// ---------------------------------------------------------------------------
__global__ void __launch_bounds__(256)
k_node_out(const float* __restrict__ Wh1, const float* __restrict__ bh1,
           const float* __restrict__ Wh2, const float* __restrict__ bh2,
           float* __restrict__ out)
{
    __shared__ float sHM[8][2*DD];
    __shared__ float sU[8][DD];
    const int r0 = blockIdx.x*8;
    const int t = threadIdx.x, c = t & 127, half = t >> 7;

    for (int idx = t; idx < 8*DD; idx += 256){
        int r = idx >> 7, cc = idx & 127;
        sHM[r][cc]      = g_h[(size_t)(r0+r)*DD + cc];
        sHM[r][DD + cc] = g_mp2[(size_t)(r0+r)*DD + cc]
                        + g_mp2[(size_t)(NROW + r0+r)*DD + cc];
    }
    __syncthreads();
    float a[4] = {0,0,0,0};
    #pragma unroll 4
    for (int k = 0; k < 2*DD; k++){
        float wv = Wh1[(size_t)k*DD + c];
        #pragma unroll
        for (int i = 0; i < 4; i++) a[i] += sHM[half*4+i][k]*wv;
    }
    const float b1 = bh1[c];
    #pragma unroll
    for (int i = 0; i < 4; i++) sU[half*4+i][c] = lrelu(a[i] + b1);
    __syncthreads();
    float a2[4] = {0,0,0,0};
    #pragma unroll 4
    for (int k = 0; k < DD; k++){
        float wv = Wh2[(size_t)k*DD + c];
        #pragma unroll
        for (int i = 0; i < 4; i++) a2[i] += sU[half*4+i][k]*wv;
    }
    const float b2 = bh2[c];
    #pragma unroll
    for (int i = 0; i < 4; i++)
        out[(size_t)(r0+half*4+i)*DD + c] = a2[i] + b2 + sHM[half*4+i][c];
}

// ---------------------------------------------------------------------------
// K4: edge kernel — fp16 m16n8k16 + ldmatrix + cp.async tj pipeline.
// 256 threads/CTA, 2 CTAs/SM.  Item = (tile, jhalf) = 128 j-rows.
// ---------------------------------------------------------------------------
__device__ __forceinline__ void prefetch_tj(const __half* __restrict__ g,
                                            int it, int t, uint32_t sTjBase){
    const int tile = it >> 1, jh = it & 1;
    const int b = tile >> 8;
    const __half* src = g + ((size_t)(b*RR + jh*JH))*DD;
    #pragma unroll
    for (int r = 0; r < 8; r++) {
        int cid = t + r*256;                // 0..2047 16B-chunks
        int row = cid >> 4, col = (cid & 15)*8;
        asm volatile("cp.async.ca.shared.global [%0], [%1], 16;"
            :: "r"(sTjBase + (uint32_t)(row*DD + col)*2),
               "l"(src + (size_t)row*DD + col) : "memory");
    }
    asm volatile("cp.async.commit_group;" ::: "memory");
}

__global__ void __launch_bounds__(256, 2)
k_edge(const float* __restrict__ be2,
       const float* __restrict__ Winf,
       const float* __restrict__ binf,
       const float* __restrict__ We1,
       const float* __restrict__ We2,
       const float* __restrict__ coords,
       int nitems)
{
    extern __shared__ char smraw[];
    __half* sWt = (__half*)smraw;                   // 34816 B  [c][k]
    __half* sXh = (__half*)(smraw + 34816);         // 34816 B  [jl][k]
    __half* sTj = (__half*)(smraw + 69632);         // 32768 B  [jl][k] raw tj
    float* sC  = (float*)(smraw + 102400);          // 3*256
    float* sEp = sC  + 3*RR;                        // 128
    float* sE  = sEp + JH;                          // 128
    float* sTi = sE  + JH;                          // 128
    float* sWd = sTi + DD;                          // 128
    float* sMp = sWd + DD;                          // 128
    float* sBc = sMp + DD;                          // 128
    float* sWc = sBc + DD;                          // 128

    const int t    = threadIdx.x;
    const int w    = t >> 5;
    const int lane = t & 31;
    const int g    = lane >> 2;
    const int tig  = lane & 3;
    const int pair = w >> 1;            // 0..3
    const int jbase = pair * 32;        // local j
    const int cbase = (w & 1) * 64;
    const int barid = 1 + pair;

    const uint32_t sTjBase = smem_u32(sTj);

    // one-time: W_e2 transposed into [c][k] halves
    for (int idx = t; idx < DD*DD; idx += 256) {
        int k = idx >> 7, c = idx & 127;
        sWt[c*SWH + k] = __float2half_rn(We2[idx]);
    }
    if (t < DD) {
        sWd[t] = We1[2*DD*DD + t];
        sBc[t] = be2[t];
        sWc[t] = Winf[t];
    }
    const float bi = binf[0];
    __syncthreads();

    // prefetch first item's tj slice
    if (blockIdx.x < nitems) prefetch_tj(g_tjh, blockIdx.x, t, sTjBase);

    // ldmatrix per-lane base addresses
    uint32_t aAddr[2];
    #pragma unroll
    for (int mi = 0; mi < 2; mi++)
        aAddr[mi] = smem_u32(&sXh[(size_t)(jbase + mi*16 + (lane & 15))*SXH
                                  + ((lane >> 4) << 3)]);
    uint32_t bAddr[4];
    #pragma unroll
    for (int nb = 0; nb < 4; nb++)
        bAddr[nb] = smem_u32(&sWt[(size_t)(cbase + nb*16 + ((lane >> 4) << 3) + (lane & 7))*SWH
                                  + (((lane >> 3) & 1) << 3)]);

    for (int item = blockIdx.x; item < nitems; item += gridDim.x) {
        const int tile = item >> 1, jhalf = item & 1;
        const int b = tile >> 8, i = tile & 255;
        const int jg0 = jhalf * JH;

        // wait for this item's tj slice
        asm volatile("cp.async.wait_group 0;" ::: "memory");
        {
            const float* cp = coords + ((size_t)b*RR + t)*3;
            sC[t] = cp[0]; sC[RR + t] = cp[1]; sC[2*RR + t] = cp[2];
        }
        if (t < DD) { sTi[t] = g_ti[(size_t)tile*DD + t]; sMp[t] = 0.f; }
        __syncthreads();   // tj visible to all; staging done

        // ---- build own 16 local X rows as fp16 (tj from SMEM) ----
        {
            const int k4 = lane*4;
            const float ti0 = sTi[k4], ti1 = sTi[k4+1], ti2 = sTi[k4+2], ti3 = sTi[k4+3];
            const float wd0 = sWd[k4], wd1 = sWd[k4+1], wd2 = sWd[k4+2], wd3 = sWd[k4+3];
            const float cix = sC[i], ciy = sC[RR + i], ciz = sC[2*RR + i];
            const int jw = jbase + (w & 1)*16;      // local
            #pragma unroll
            for (int jj = 0; jj < 16; jj += 2) {
                const int jl = jw + jj, jl1 = jw + jj + 1;
                const int jA = jg0 + jl, jB = jg0 + jl1;
                uint2 rv0 = *(const uint2*)&sTj[(size_t)jl *DD + k4];
                uint2 rv1 = *(const uint2*)&sTj[(size_t)jl1*DD + k4];
                float2 f01 = __half22float2(*(__half2*)&rv0.x);
                float2 f23 = __half22float2(*(__half2*)&rv0.y);
                float2 g01 = __half22float2(*(__half2*)&rv1.x);
                float2 g23 = __half22float2(*(__half2*)&rv1.y);
                float dx0 = sC[jA] - cix, dy0 = sC[RR+jA] - ciy, dz0 = sC[2*RR+jA] - ciz;
                float dx1 = sC[jB] - cix, dy1 = sC[RR+jB] - ciy, dz1 = sC[2*RR+jB] - ciz;
                float d20 = dx0*dx0 + dy0*dy0 + dz0*dz0;
                float d21 = dx1*dx1 + dy1*dy1 + dz1*dz1;
                __half2 h01 = __floats2half2_rn(lrelu(ti0 + f01.x + d20*wd0),
                                                lrelu(ti1 + f01.y + d20*wd1));
                __half2 h23 = __floats2half2_rn(lrelu(ti2 + f23.x + d20*wd2),
                                                lrelu(ti3 + f23.y + d20*wd3));
                uint2 u0; u0.x = *(uint32_t*)&h01; u0.y = *(uint32_t*)&h23;
                *(uint2*)&sXh[(size_t)jl*SXH + k4] = u0;
                __half2 h45 = __floats2half2_rn(lrelu(ti0 + g01.x + d21*wd0),
                                                lrelu(ti1 + g01.y + d21*wd1));
                __half2 h67 = __floats2half2_rn(lrelu(ti2 + g23.x + d21*wd2),
                                                lrelu(ti3 + g23.y + d21*wd3));
                uint2 u1; u1.x = *(uint32_t*)&h45; u1.y = *(uint32_t*)&h67;
                *(uint2*)&sXh[(size_t)jl1*SXH + k4] = u1;
            }
        }
        if ((w & 1) == 0) sEp[jbase + lane] = 0.f;
        __syncthreads();   // all X written AND all sTj reads done

        // kick off next item's tj prefetch (overlaps MMA + epilogue)
        {
            int nx = item + gridDim.x;
            if (nx < nitems) prefetch_tj(g_tjh, nx, t, sTjBase);
        }

        // ---- mainloop: 32x64 warp tile, ldmatrix + m16n8k16 fp16 ----
        float acc[2][8][4];
        #pragma unroll
        for (int mi = 0; mi < 2; mi++)
            #pragma unroll
            for (int ni = 0; ni < 8; ni++)
                #pragma unroll
                for (int q = 0; q < 4; q++) acc[mi][ni][q] = 0.f;

        #pragma unroll
        for (int k0 = 0; k0 < DD; k0 += 16) {
            const uint32_t kb = k0*2;
            uint32_t A[2][4];
            #pragma unroll
            for (int mi = 0; mi < 2; mi++)
                ldsm_x4(A[mi][0], A[mi][1], A[mi][2], A[mi][3], aAddr[mi] + kb);
            uint32_t Bf[8][2];
            #pragma unroll
            for (int nb = 0; nb < 4; nb++)
                ldsm_x4(Bf[nb*2][0], Bf[nb*2][1], Bf[nb*2+1][0], Bf[nb*2+1][1],
                        bAddr[nb] + kb);
            #pragma unroll
            for (int mi = 0; mi < 2; mi++)
                #pragma unroll
                for (int ni = 0; ni < 8; ni++)
                    asm volatile(
                        "mma.sync.aligned.m16n8k16.row.col.f32.f16.f16.f32 "
                        "{%0,%1,%2,%3}, {%4,%5,%6,%7}, {%8,%9}, {%0,%1,%2,%3};"
                        : "+f"(acc[mi][ni][0]), "+f"(acc[mi][ni][1]),
                          "+f"(acc[mi][ni][2]), "+f"(acc[mi][ni][3])
                        : "r"(A[mi][0]), "r"(A[mi][1]), "r"(A[mi][2]), "r"(A[mi][3]),
                          "r"(Bf[ni][0]), "r"(Bf[ni][1]));
        }

        // ---- epilogue: convert acc -> m in place, then two passes ----
        float bc[16], wc[16];
        #pragma unroll
        for (int ni = 0; ni < 8; ni++)
            #pragma unroll
            for (int q = 0; q < 2; q++) {
                int c = cbase + ni*8 + tig*2 + q;
                bc[ni*2+q] = sBc[c];
                wc[ni*2+q] = sWc[c];
            }
        #pragma unroll
        for (int mi = 0; mi < 2; mi++)
            #pragma unroll
            for (int ni = 0; ni < 8; ni++)
                #pragma unroll
                for (int q4 = 0; q4 < 4; q4++)
                    acc[mi][ni][q4] = lrelu(acc[mi][ni][q4] + bc[ni*2 + (q4 & 1)]);

        // pass 1: per-j gate logit partials
        #pragma unroll
        for (int mi = 0; mi < 2; mi++)
            #pragma unroll
            for (int r = 0; r < 2; r++) {
                float p = 0.f;
                #pragma unroll
                for (int ni = 0; ni < 8; ni++)
                    #pragma unroll
                    for (int q = 0; q < 2; q++)
                        p += acc[mi][ni][r*2+q] * wc[ni*2+q];
                p += __shfl_xor_sync(0xffffffffu, p, 1);
                p += __shfl_xor_sync(0xffffffffu, p, 2);
                if (tig == 0) atomicAdd(&sEp[jbase + mi*16 + g + r*8], p);
            }
        pair_bar(barid);
        if ((w & 1) == 0) {
            int jl = jbase + lane;
            float s = sEp[jl] + bi;
            sE[jl] = ((jg0 + jl) == i) ? 0.f : __fdividef(1.f, 1.f + __expf(-s));
        }
        pair_bar(barid);

        // pass 2: mpre[c] = sum_j m*e
        float macc[16];
        #pragma unroll
        for (int q = 0; q < 16; q++) macc[q] = 0.f;
        #pragma unroll
        for (int mi = 0; mi < 2; mi++)
            #pragma unroll
            for (int r = 0; r < 2; r++) {
                float e = sE[jbase + mi*16 + g + r*8];
                #pragma unroll
                for (int ni = 0; ni < 8; ni++)
                    #pragma unroll
                    for (int q = 0; q < 2; q++)
                        macc[ni*2+q] += acc[mi][ni][r*2+q] * e;
            }
        #pragma unroll
        for (int q = 0; q < 16; q++) {
            macc[q] += __shfl_xor_sync(0xffffffffu, macc[q], 4);
            macc[q] += __shfl_xor_sync(0xffffffffu, macc[q], 8);
            macc[q] += __shfl_xor_sync(0xffffffffu, macc[q], 16);
        }
        if (g == 0) {
            #pragma unroll
            for (int q = 0; q < 16; q++)
                atomicAdd(&sMp[cbase + (q >> 1)*8 + tig*2 + (q & 1)], macc[q]);
        }
        __syncthreads();
        if (t < DD) g_mp2[(size_t)(jhalf*NROW + tile)*DD + t] = sMp[t];
        __syncthreads();
    }
}

// ---------------------------------------------------------------------------
extern "C" void kernel_launch(void* const* d_in, const int* in_sizes, int n_in,
                              void* d_out, int out_size)
{
    const float* fres   = (const float*)d_in[0];
    const float* coords = (const float*)d_in[1];
    const float* Wemb   = (const float*)d_in[2];
    const float* We1    = (const float*)d_in[3];
    const float* be1    = (const float*)d_in[4];
    const float* We2    = (const float*)d_in[5];
    const float* be2    = (const float*)d_in[6];
    const float* Winf   = (const float*)d_in[7];
    const float* binf   = (const float*)d_in[8];
    const float* Wh1    = (const float*)d_in[9];
    const float* bh1    = (const float*)d_in[10];
    const float* Wh2    = (const float*)d_in[11];
    const float* bh2    = (const float*)d_in[12];
    float* out = (float*)d_out;

    const int EDGE_SMEM = 102400 + (3*RR + 2*JH + 5*DD)*(int)sizeof(float);  // 109056
    cudaFuncSetAttribute(k_edge, cudaFuncAttributeMaxDynamicSharedMemorySize, EDGE_SMEM);

    k_embed_titj<<<NROW/8, 256>>>(fres, Wemb, We1, be1);
    k_edge<<<296, 256, EDGE_SMEM>>>(be2, Winf, binf, We1, We2, coords, NROW*2);
    k_node_titj<<<NROW/8, 256>>>(Wh1, bh1, Wh2, bh2, We1, be1);
    k_edge<<<296, 256, EDGE_SMEM>>>(be2, Winf, binf, We1, We2, coords, NROW*2);
    k_node_out<<<NROW/8, 256>>>(Wh1, bh1, Wh2, bh2, out);
}

// round 14
// speedup vs baseline: 1.0360x; 1.0360x over previous
#include <cuda_runtime.h>
#include <cuda_fp16.h>
#include <cstdint>
#include <math.h>

#define BB 8
#define RR 256
#define DD 128
#define NROW (BB*RR)
#define NEG 0.1f
#define SXH 136            // X row stride (halves): 272B = 17x16B (odd) -> ldmatrix conflict-free
#define SWH 136            // Wt row stride (halves): same property
#define JH 128             // j rows per CTA (half tile)

// Persistent scratch (no allocations allowed)
__device__ float g_h[NROW*DD];
__device__ float g_ti[NROW*DD];
__device__ float g_tj[NROW*DD];
__device__ float g_mp2[2*NROW*DD];   // per-jhalf partial mpre

__device__ __forceinline__ float lrelu(float x){ return x > 0.f ? x : NEG*x; }

__device__ __forceinline__ void pair_bar(int id){
    asm volatile("bar.sync %0, %1;" :: "r"(id), "r"(64) : "memory");
}
__device__ __forceinline__ uint32_t smem_u32(const void* p){
    return (uint32_t)__cvta_generic_to_shared(p);
}
__device__ __forceinline__ void ldsm_x4(uint32_t& r0, uint32_t& r1, uint32_t& r2, uint32_t& r3,
                                        uint32_t addr){
    asm volatile("ldmatrix.sync.aligned.m8n8.x4.shared.b16 {%0,%1,%2,%3}, [%4];"
        : "=r"(r0), "=r"(r1), "=r"(r2), "=r"(r3) : "r"(addr));
}

// ---------------------------------------------------------------------------
// F1: fused embed + titj.  8 rows/block, 256 threads = 128 cols x 2 halves.
// ---------------------------------------------------------------------------
__global__ void __launch_bounds__(256)
k_embed_titj(const float* __restrict__ fres, const float* __restrict__ Wemb,
             const float* __restrict__ We1, const float* __restrict__ be1)
{
    __shared__ float sF[8][20];
    __shared__ float sH[8][DD];
    const int r0 = blockIdx.x*8;
    const int t = threadIdx.x, c = t & 127, half = t >> 7;

    for (int idx = t; idx < 8*20; idx += 256)
        sF[idx/20][idx%20] = fres[(size_t)(r0 + idx/20)*20 + idx%20];
    __syncthreads();

    {   // embed: 4 rows per thread
        float a[4] = {0,0,0,0};
        #pragma unroll
        for (int k = 0; k < 20; k++){
            float wv = Wemb[k*DD + c];
            #pragma unroll
            for (int i = 0; i < 4; i++) a[i] += sF[half*4+i][k]*wv;
        }
        #pragma unroll
        for (int i = 0; i < 4; i++){
            float hv = lrelu(a[i]);
            sH[half*4+i][c] = hv;
            g_h[(size_t)(r0+half*4+i)*DD + c] = hv;
        }
    }
    __syncthreads();

    {   // titj: 8 rows per thread; half 0 -> ti, half 1 -> tj
        const float* W = We1 + (size_t)half*DD*DD;
        float a[8] = {0,0,0,0,0,0,0,0};
        #pragma unroll 4
        for (int k = 0; k < DD; k++){
            float wv = W[(size_t)k*DD + c];
            #pragma unroll
            for (int r = 0; r < 8; r++) a[r] += sH[r][k]*wv;
        }
        if (half == 0){
            const float be = be1[c];
            #pragma unroll
            for (int r = 0; r < 8; r++) g_ti[(size_t)(r0+r)*DD + c] = a[r] + be;
        } else {
            #pragma unroll
            for (int r = 0; r < 8; r++) g_tj[(size_t)(r0+r)*DD + c] = a[r];
        }
    }
}

// ---------------------------------------------------------------------------
// F2: fused node update (u1,u2) + titj for the next iteration.  8 rows/block.
// ---------------------------------------------------------------------------
__global__ void __launch_bounds__(256)
k_node_titj(const float* __restrict__ Wh1, const float* __restrict__ bh1,
            const float* __restrict__ Wh2, const float* __restrict__ bh2,
            const float* __restrict__ We1, const float* __restrict__ be1)
{
    __shared__ float sHM[8][2*DD];   // [h | mpre]
    __shared__ float sU[8][DD];
    __shared__ float sHN[8][DD];
    const int r0 = blockIdx.x*8;
    const int t = threadIdx.x, c = t & 127, half = t >> 7;

    for (int idx = t; idx < 8*DD; idx += 256){
        int r = idx >> 7, cc = idx & 127;
        sHM[r][cc]      = g_h[(size_t)(r0+r)*DD + cc];
        sHM[r][DD + cc] = g_mp2[(size_t)(r0+r)*DD + cc]
                        + g_mp2[(size_t)(NROW + r0+r)*DD + cc];
    }
    __syncthreads();

    {   // u1: 4 rows per thread, K=256
        float a[4] = {0,0,0,0};
        #pragma unroll 4
        for (int k = 0; k < 2*DD; k++){
            float wv = Wh1[(size_t)k*DD + c];
            #pragma unroll
            for (int i = 0; i < 4; i++) a[i] += sHM[half*4+i][k]*wv;
        }
        const float b1 = bh1[c];
        #pragma unroll
        for (int i = 0; i < 4; i++) sU[half*4+i][c] = lrelu(a[i] + b1);
    }
    __syncthreads();

    {   // u2 + residual: 4 rows per thread
        float a[4] = {0,0,0,0};
        #pragma unroll 4
        for (int k = 0; k < DD; k++){
            float wv = Wh2[(size_t)k*DD + c];
            #pragma unroll
            for (int i = 0; i < 4; i++) a[i] += sU[half*4+i][k]*wv;
        }
        const float b2 = bh2[c];
        #pragma unroll
        for (int i = 0; i < 4; i++){
            float hn = a[i] + b2 + sHM[half*4+i][c];
            sHN[half*4+i][c] = hn;
            g_h[(size_t)(r0+half*4+i)*DD + c] = hn;
        }
    }
    __syncthreads();

    {   // titj on updated h: 8 rows per thread
        const float* W = We1 + (size_t)half*DD*DD;
        float a[8] = {0,0,0,0,0,0,0,0};
        #pragma unroll 4
        for (int k = 0; k < DD; k++){
            float wv = W[(size_t)k*DD + c];
            #pragma unroll
            for (int r = 0; r < 8; r++) a[r] += sHN[r][k]*wv;
        }
        if (half == 0){
            const float be = be1[c];
            #pragma unroll
            for (int r = 0; r < 8; r++) g_ti[(size_t)(r0+r)*DD + c] = a[r] + be;
        } else {
            #pragma unroll
            for (int r = 0; r < 8; r++) g_tj[(size_t)(r0+r)*DD + c] = a[r];
        }
    }
}

// ---------------------------------------------------------------------------
// F3: final node update -> out.  8 rows/block.
// ---------------------------------------------------------------------------
__global__ void __launch_bounds__(256)
k_node_out(const float* __restrict__ Wh1, const float* __restrict__ bh1,
           const float* __restrict__ Wh2, const float* __restrict__ bh2,
           float* __restrict__ out)
{
    __shared__ float sHM[8][2*DD];
    __shared__ float sU[8][DD];
    const int r0 = blockIdx.x*8;
    const int t = threadIdx.x, c = t & 127, half = t >> 7;

    for (int idx = t; idx < 8*DD; idx += 256){
        int r = idx >> 7, cc = idx & 127;
        sHM[r][cc]      = g_h[(size_t)(r0+r)*DD + cc];
        sHM[r][DD + cc] = g_mp2[(size_t)(r0+r)*DD + cc]
                        + g_mp2[(size_t)(NROW + r0+r)*DD + cc];
    }
    __syncthreads();
    float a[4] = {0,0,0,0};
    #pragma unroll 4
    for (int k = 0; k < 2*DD; k++){
        float wv = Wh1[(size_t)k*DD + c];
        #pragma unroll
        for (int i = 0; i < 4; i++) a[i] += sHM[half*4+i][k]*wv;
    }
    const float b1 = bh1[c];
    #pragma unroll
    for (int i = 0; i < 4; i++) sU[half*4+i][c] = lrelu(a[i] + b1);
    __syncthreads();
    float a2[4] = {0,0,0,0};
    #pragma unroll 4
    for (int k = 0; k < DD; k++){
        float wv = Wh2[(size_t)k*DD + c];
        #pragma unroll
        for (int i = 0; i < 4; i++) a2[i] += sU[half*4+i][k]*wv;
    }
    const float b2 = bh2[c];
    #pragma unroll
    for (int i = 0; i < 4; i++)
        out[(size_t)(r0+half*4+i)*DD + c] = a2[i] + b2 + sHM[half*4+i][c];
}

// ---------------------------------------------------------------------------
// K4: edge kernel — fp16 m16n8k16 + ldmatrix.  256 threads/CTA, 2 CTAs/SM.
// Item = (tile, jhalf) = 128 j-rows.  All-batch coords cached once in SMEM.
// ---------------------------------------------------------------------------
__global__ void __launch_bounds__(256, 2)
k_edge(const float* __restrict__ be2,
       const float* __restrict__ Winf,
       const float* __restrict__ binf,
       const float* __restrict__ We1,
       const float* __restrict__ We2,
       const float* __restrict__ coords,
       int nitems)
{
    extern __shared__ char smraw[];
    __half* sWt  = (__half*)smraw;                  // 34816 B  [c][k]
    __half* sXh  = (__half*)(smraw + 34816);        // 34816 B  [jl][k]
    float* sCall = (float*)(smraw + 69632);         // 8*768 = 24576 B (all-batch coords)
    float* sEp = sCall + BB*3*RR;                   // 128
    float* sE  = sEp + JH;                          // 128
    float* sTi = sE  + JH;                          // 128
    float* sWd = sTi + DD;                          // 128
    float* sMp = sWd + DD;                          // 128
    float* sBc = sMp + DD;                          // 128
    float* sWc = sBc + DD;                          // 128

    const int t    = threadIdx.x;
    const int w    = t >> 5;
    const int lane = t & 31;
    const int g    = lane >> 2;
    const int tig  = lane & 3;
    const int pair = w >> 1;            // 0..3
    const int jbase = pair * 32;        // local j
    const int cbase = (w & 1) * 64;
    const int barid = 1 + pair;

    // one-time: W_e2 transposed into [c][k] halves
    for (int idx = t; idx < DD*DD; idx += 256) {
        int k = idx >> 7, c = idx & 127;
        sWt[c*SWH + k] = __float2half_rn(We2[idx]);
    }
    // one-time: all 8 batches' coords (layout: [b][xyz][256])
    for (int idx = t; idx < BB*RR; idx += 256) {
        int b = idx >> 8, j = idx & 255;
        const float* cp = coords + (size_t)idx*3;
        sCall[b*768 + j]        = cp[0];
        sCall[b*768 + 256 + j]  = cp[1];
        sCall[b*768 + 512 + j]  = cp[2];
    }
    if (t < DD) {
        sWd[t] = We1[2*DD*DD + t];
        sBc[t] = be2[t];
        sWc[t] = Winf[t];
    }
    const float bi = binf[0];
    __syncthreads();

    // ldmatrix per-lane base addresses (fixed across items)
    uint32_t aAddr[2];
    #pragma unroll
    for (int mi = 0; mi < 2; mi++)
        aAddr[mi] = smem_u32(&sXh[(size_t)(jbase + mi*16 + (lane & 15))*SXH
                                  + ((lane >> 4) << 3)]);
    uint32_t bAddr[4];
    #pragma unroll
    for (int nb = 0; nb < 4; nb++)
        bAddr[nb] = smem_u32(&sWt[(size_t)(cbase + nb*16 + ((lane >> 4) << 3) + (lane & 7))*SWH
                                  + (((lane >> 3) & 1) << 3)]);

    for (int item = blockIdx.x; item < nitems; item += gridDim.x) {
        const int tile = item >> 1, jhalf = item & 1;
        const int b = tile >> 8, i = tile & 255;
        const int jg0 = jhalf * JH;
        const float* sC = sCall + b*768;

        if (t < DD) { sTi[t] = g_ti[(size_t)tile*DD + t]; sMp[t] = 0.f; }
        __syncthreads();

        // ---- build own 16 local X rows as fp16 ----
        {
            const float* tjb = g_tj + (size_t)b*RR*DD;
            const int k4 = lane*4;
            const float ti0 = sTi[k4], ti1 = sTi[k4+1], ti2 = sTi[k4+2], ti3 = sTi[k4+3];
            const float wd0 = sWd[k4], wd1 = sWd[k4+1], wd2 = sWd[k4+2], wd3 = sWd[k4+3];
            const float cix = sC[i], ciy = sC[256 + i], ciz = sC[512 + i];
            const int jw = jbase + (w & 1)*16;      // local
            #pragma unroll
            for (int jj = 0; jj < 16; jj += 2) {
                const int jl = jw + jj, jl1 = jw + jj + 1;
                const int jA = jg0 + jl, jB = jg0 + jl1;   // global
                float4 tv0 = *(const float4*)&tjb[(size_t)jA*DD + k4];
                float4 tv1 = *(const float4*)&tjb[(size_t)jB*DD + k4];
                float dx0 = sC[jA] - cix, dy0 = sC[256+jA] - ciy, dz0 = sC[512+jA] - ciz;
                float dx1 = sC[jB] - cix, dy1 = sC[256+jB] - ciy, dz1 = sC[512+jB] - ciz;
                float d20 = dx0*dx0 + dy0*dy0 + dz0*dz0;
                float d21 = dx1*dx1 + dy1*dy1 + dz1*dz1;
                __half2 h01 = __floats2half2_rn(lrelu(ti0 + tv0.x + d20*wd0),
                                                lrelu(ti1 + tv0.y + d20*wd1));
                __half2 h23 = __floats2half2_rn(lrelu(ti2 + tv0.z + d20*wd2),
                                                lrelu(ti3 + tv0.w + d20*wd3));
                uint2 u0; u0.x = *(uint32_t*)&h01; u0.y = *(uint32_t*)&h23;
                *(uint2*)&sXh[(size_t)jl*SXH + k4] = u0;
                __half2 h45 = __floats2half2_rn(lrelu(ti0 + tv1.x + d21*wd0),
                                                lrelu(ti1 + tv1.y + d21*wd1));
                __half2 h67 = __floats2half2_rn(lrelu(ti2 + tv1.z + d21*wd2),
                                                lrelu(ti3 + tv1.w + d21*wd3));
                uint2 u1; u1.x = *(uint32_t*)&h45; u1.y = *(uint32_t*)&h67;
                *(uint2*)&sXh[(size_t)jl1*SXH + k4] = u1;
            }
        }
        if ((w & 1) == 0) sEp[jbase + lane] = 0.f;
        pair_bar(barid);

        // ---- mainloop: 32x64 warp tile, ldmatrix + m16n8k16 fp16 ----
        float acc[2][8][4];
        #pragma unroll
        for (int mi = 0; mi < 2; mi++)
            #pragma unroll
            for (int ni = 0; ni < 8; ni++)
                #pragma unroll
                for (int q = 0; q < 4; q++) acc[mi][ni][q] = 0.f;

        #pragma unroll
        for (int k0 = 0; k0 < DD; k0 += 16) {
            const uint32_t kb = k0*2;
            uint32_t A[2][4];
            #pragma unroll
            for (int mi = 0; mi < 2; mi++)
                ldsm_x4(A[mi][0], A[mi][1], A[mi][2], A[mi][3], aAddr[mi] + kb);
            uint32_t Bf[8][2];
            #pragma unroll
            for (int nb = 0; nb < 4; nb++)
                ldsm_x4(Bf[nb*2][0], Bf[nb*2][1], Bf[nb*2+1][0], Bf[nb*2+1][1],
                        bAddr[nb] + kb);
            #pragma unroll
            for (int mi = 0; mi < 2; mi++)
                #pragma unroll
                for (int ni = 0; ni < 8; ni++)
                    asm volatile(
                        "mma.sync.aligned.m16n8k16.row.col.f32.f16.f16.f32 "
                        "{%0,%1,%2,%3}, {%4,%5,%6,%7}, {%8,%9}, {%0,%1,%2,%3};"
                        : "+f"(acc[mi][ni][0]), "+f"(acc[mi][ni][1]),
                          "+f"(acc[mi][ni][2]), "+f"(acc[mi][ni][3])
                        : "r"(A[mi][0]), "r"(A[mi][1]), "r"(A[mi][2]), "r"(A[mi][3]),
                          "r"(Bf[ni][0]), "r"(Bf[ni][1]));
        }

        // ---- epilogue: convert acc -> m in place, then two passes ----
        float bc[16], wc[16];
        #pragma unroll
        for (int ni = 0; ni < 8; ni++)
            #pragma unroll
            for (int q = 0; q < 2; q++) {
                int c = cbase + ni*8 + tig*2 + q;
                bc[ni*2+q] = sBc[c];
                wc[ni*2+q] = sWc[c];
            }
        #pragma unroll
        for (int mi = 0; mi < 2; mi++)
            #pragma unroll
            for (int ni = 0; ni < 8; ni++)
                #pragma unroll
                for (int q4 = 0; q4 < 4; q4++)
                    acc[mi][ni][q4] = lrelu(acc[mi][ni][q4] + bc[ni*2 + (q4 & 1)]);

        // pass 1: per-j gate logit partials
        #pragma unroll
        for (int mi = 0; mi < 2; mi++)
            #pragma unroll
            for (int r = 0; r < 2; r++) {
                float p = 0.f;
                #pragma unroll
                for (int ni = 0; ni < 8; ni++)
                    #pragma unroll
                    for (int q = 0; q < 2; q++)
                        p += acc[mi][ni][r*2+q] * wc[ni*2+q];
                p += __shfl_xor_sync(0xffffffffu, p, 1);
                p += __shfl_xor_sync(0xffffffffu, p, 2);
                if (tig == 0) atomicAdd(&sEp[jbase + mi*16 + g + r*8], p);
            }
        pair_bar(barid);
        if ((w & 1) == 0) {
            int jl = jbase + lane;
            float s = sEp[jl] + bi;
            sE[jl] = ((jg0 + jl) == i) ? 0.f : __fdividef(1.f, 1.f + __expf(-s));
        }
        pair_bar(barid);

        // pass 2: mpre[c] = sum_j m*e
        float macc[16];
        #pragma unroll
        for (int q = 0; q < 16; q++) macc[q] = 0.f;
        #pragma unroll
        for (int mi = 0; mi < 2; mi++)
            #pragma unroll
            for (int r = 0; r < 2; r++) {
                float e = sE[jbase + mi*16 + g + r*8];
                #pragma unroll
                for (int ni = 0; ni < 8; ni++)
                    #pragma unroll
                    for (int q = 0; q < 2; q++)
                        macc[ni*2+q] += acc[mi][ni][r*2+q] * e;
            }
        #pragma unroll
        for (int q = 0; q < 16; q++) {
            macc[q] += __shfl_xor_sync(0xffffffffu, macc[q], 4);
            macc[q] += __shfl_xor_sync(0xffffffffu, macc[q], 8);
            macc[q] += __shfl_xor_sync(0xffffffffu, macc[q], 16);
        }
        if (g == 0) {
            #pragma unroll
            for (int q = 0; q < 16; q++)
                atomicAdd(&sMp[cbase + (q >> 1)*8 + tig*2 + (q & 1)], macc[q]);
        }
        __syncthreads();
        if (t < DD) g_mp2[(size_t)(jhalf*NROW + tile)*DD + t] = sMp[t];
        __syncthreads();
    }
}

// ---------------------------------------------------------------------------
extern "C" void kernel_launch(void* const* d_in, const int* in_sizes, int n_in,
                              void* d_out, int out_size)
{
    const float* fres   = (const float*)d_in[0];
    const float* coords = (const float*)d_in[1];
    const float* Wemb   = (const float*)d_in[2];
    const float* We1    = (const float*)d_in[3];
    const float* be1    = (const float*)d_in[4];
    const float* We2    = (const float*)d_in[5];
    const float* be2    = (const float*)d_in[6];
    const float* Winf   = (const float*)d_in[7];
    const float* binf   = (const float*)d_in[8];
    const float* Wh1    = (const float*)d_in[9];
    const float* bh1    = (const float*)d_in[10];
    const float* Wh2    = (const float*)d_in[11];
    const float* bh2    = (const float*)d_in[12];
    float* out = (float*)d_out;

    const int EDGE_SMEM = 69632 + (BB*3*RR + 2*JH + 5*DD)*(int)sizeof(float);  // 97792
    cudaFuncSetAttribute(k_edge, cudaFuncAttributeMaxDynamicSharedMemorySize, EDGE_SMEM);

    k_embed_titj<<<NROW/8, 256>>>(fres, Wemb, We1, be1);
    k_edge<<<296, 256, EDGE_SMEM>>>(be2, Winf, binf, We1, We2, coords, NROW*2);
    k_node_titj<<<NROW/8, 256>>>(Wh1, bh1, Wh2, bh2, We1, be1);
    k_edge<<<296, 256, EDGE_SMEM>>>(be2, Winf, binf, We1, We2, coords, NROW*2);
    k_node_out<<<NROW/8, 256>>>(Wh1, bh1, Wh2, bh2, out);
}

// round 15
// speedup vs baseline: 1.1464x; 1.1066x over previous
#include <cuda_runtime.h>
#include <cuda_fp16.h>
#include <cstdint>
#include <math.h>

#define BB 8
#define RR 256
#define DD 128
#define NROW (BB*RR)
#define NEG 0.1f
#define SXH 136            // X row stride (halves): 272B = 17x16B (odd) -> ldmatrix conflict-free
#define SWH 136            // Wt row stride (halves): same property
#define JH 128             // j rows per CTA (half tile)

// Persistent scratch (no allocations allowed)
__device__ float g_h[NROW*DD];
__device__ float g_ti[NROW*DD];
__device__ float g_tj[NROW*DD];
__device__ float g_mp8[8*NROW*DD];   // per-(pair,jhalf) partial mpre slabs

__device__ __forceinline__ float lrelu(float x){ return x > 0.f ? x : NEG*x; }

__device__ __forceinline__ void pair_bar(int id){
    asm volatile("bar.sync %0, %1;" :: "r"(id), "r"(64) : "memory");
}
__device__ __forceinline__ uint32_t smem_u32(const void* p){
    return (uint32_t)__cvta_generic_to_shared(p);
}
__device__ __forceinline__ void ldsm_x4(uint32_t& r0, uint32_t& r1, uint32_t& r2, uint32_t& r3,
                                        uint32_t addr){
    asm volatile("ldmatrix.sync.aligned.m8n8.x4.shared.b16 {%0,%1,%2,%3}, [%4];"
        : "=r"(r0), "=r"(r1), "=r"(r2), "=r"(r3) : "r"(addr));
}

// ---------------------------------------------------------------------------
// F1: fused embed + titj.  8 rows/block, 256 threads = 128 cols x 2 halves.
// ---------------------------------------------------------------------------
__global__ void __launch_bounds__(256)
k_embed_titj(const float* __restrict__ fres, const float* __restrict__ Wemb,
             const float* __restrict__ We1, const float* __restrict__ be1)
{
    __shared__ float sF[8][20];
    __shared__ float sH[8][DD];
    const int r0 = blockIdx.x*8;
    const int t = threadIdx.x, c = t & 127, half = t >> 7;

    for (int idx = t; idx < 8*20; idx += 256)
        sF[idx/20][idx%20] = fres[(size_t)(r0 + idx/20)*20 + idx%20];
    __syncthreads();

    {   // embed: 4 rows per thread
        float a[4] = {0,0,0,0};
        #pragma unroll
        for (int k = 0; k < 20; k++){
            float wv = Wemb[k*DD + c];
            #pragma unroll
            for (int i = 0; i < 4; i++) a[i] += sF[half*4+i][k]*wv;
        }
        #pragma unroll
        for (int i = 0; i < 4; i++){
            float hv = lrelu(a[i]);
            sH[half*4+i][c] = hv;
            g_h[(size_t)(r0+half*4+i)*DD + c] = hv;
        }
    }
    __syncthreads();

    {   // titj: 8 rows per thread; half 0 -> ti, half 1 -> tj
        const float* W = We1 + (size_t)half*DD*DD;
        float a[8] = {0,0,0,0,0,0,0,0};
        #pragma unroll 4
        for (int k = 0; k < DD; k++){
            float wv = W[(size_t)k*DD + c];
            #pragma unroll
            for (int r = 0; r < 8; r++) a[r] += sH[r][k]*wv;
        }
        if (half == 0){
            const float be = be1[c];
            #pragma unroll
            for (int r = 0; r < 8; r++) g_ti[(size_t)(r0+r)*DD + c] = a[r] + be;
        } else {
            #pragma unroll
            for (int r = 0; r < 8; r++) g_tj[(size_t)(r0+r)*DD + c] = a[r];
        }
    }
}

// ---------------------------------------------------------------------------
// F2: fused node update (u1,u2) + titj for the next iteration.  8 rows/block.
// ---------------------------------------------------------------------------
__global__ void __launch_bounds__(256)
k_node_titj(const float* __restrict__ Wh1, const float* __restrict__ bh1,
            const float* __restrict__ Wh2, const float* __restrict__ bh2,
            const float* __restrict__ We1, const float* __restrict__ be1)
{
    __shared__ float sHM[8][2*DD];   // [h | mpre]
    __shared__ float sU[8][DD];
    __shared__ float sHN[8][DD];
    const int r0 = blockIdx.x*8;
    const int t = threadIdx.x, c = t & 127, half = t >> 7;

    for (int idx = t; idx < 8*DD; idx += 256){
        int r = idx >> 7, cc = idx & 127;
        sHM[r][cc] = g_h[(size_t)(r0+r)*DD + cc];
        float mp = 0.f;
        #pragma unroll
        for (int s = 0; s < 8; s++)
            mp += g_mp8[((size_t)s*NROW + (r0+r))*DD + cc];
        sHM[r][DD + cc] = mp;
    }
    __syncthreads();

    {   // u1: 4 rows per thread, K=256
        float a[4] = {0,0,0,0};
        #pragma unroll 4
        for (int k = 0; k < 2*DD; k++){
            float wv = Wh1[(size_t)k*DD + c];
            #pragma unroll
            for (int i = 0; i < 4; i++) a[i] += sHM[half*4+i][k]*wv;
        }
        const float b1 = bh1[c];
        #pragma unroll
        for (int i = 0; i < 4; i++) sU[half*4+i][c] = lrelu(a[i] + b1);
    }
    __syncthreads();

    {   // u2 + residual: 4 rows per thread
        float a[4] = {0,0,0,0};
        #pragma unroll 4
        for (int k = 0; k < DD; k++){
            float wv = Wh2[(size_t)k*DD + c];
            #pragma unroll
            for (int i = 0; i < 4; i++) a[i] += sU[half*4+i][k]*wv;
        }
        const float b2 = bh2[c];
        #pragma unroll
        for (int i = 0; i < 4; i++){
            float hn = a[i] + b2 + sHM[half*4+i][c];
            sHN[half*4+i][c] = hn;
            g_h[(size_t)(r0+half*4+i)*DD + c] = hn;
        }
    }
    __syncthreads();

    {   // titj on updated h: 8 rows per thread
        const float* W = We1 + (size_t)half*DD*DD;
        float a[8] = {0,0,0,0,0,0,0,0};
        #pragma unroll 4
        for (int k = 0; k < DD; k++){
            float wv = W[(size_t)k*DD + c];
            #pragma unroll
            for (int r = 0; r < 8; r++) a[r] += sHN[r][k]*wv;
        }
        if (half == 0){
            const float be = be1[c];
            #pragma unroll
            for (int r = 0; r < 8; r++) g_ti[(size_t)(r0+r)*DD + c] = a[r] + be;
        } else {
            #pragma unroll
            for (int r = 0; r < 8; r++) g_tj[(size_t)(r0+r)*DD + c] = a[r];
        }
    }
}

// ---------------------------------------------------------------------------
// F3: final node update -> out.  8 rows/block.
// ---------------------------------------------------------------------------
__global__ void __launch_bounds__(256)
k_node_out(const float* __restrict__ Wh1, const float* __restrict__ bh1,
           const float* __restrict__ Wh2, const float* __restrict__ bh2,
           float* __restrict__ out)
{
    __shared__ float sHM[8][2*DD];
    __shared__ float sU[8][DD];
    const int r0 = blockIdx.x*8;
    const int t = threadIdx.x, c = t & 127, half = t >> 7;

    for (int idx = t; idx < 8*DD; idx += 256){
        int r = idx >> 7, cc = idx & 127;
        sHM[r][cc] = g_h[(size_t)(r0+r)*DD + cc];
        float mp = 0.f;
        #pragma unroll
        for (int s = 0; s < 8; s++)
            mp += g_mp8[((size_t)s*NROW + (r0+r))*DD + cc];
        sHM[r][DD + cc] = mp;
    }
    __syncthreads();
    float a[4] = {0,0,0,0};
    #pragma unroll 4
    for (int k = 0; k < 2*DD; k++){
        float wv = Wh1[(size_t)k*DD + c];
        #pragma unroll
        for (int i = 0; i < 4; i++) a[i] += sHM[half*4+i][k]*wv;
    }
    const float b1 = bh1[c];
    #pragma unroll
    for (int i = 0; i < 4; i++) sU[half*4+i][c] = lrelu(a[i] + b1);
    __syncthreads();
    float a2[4] = {0,0,0,0};
    #pragma unroll 4
    for (int k = 0; k < DD; k++){
        float wv = Wh2[(size_t)k*DD + c];
        #pragma unroll
        for (int i = 0; i < 4; i++) a2[i] += sU[half*4+i][k]*wv;
    }
    const float b2 = bh2[c];
    #pragma unroll
    for (int i = 0; i < 4; i++)
        out[(size_t)(r0+half*4+i)*DD + c] = a2[i] + b2 + sHM[half*4+i][c];
}

// ---------------------------------------------------------------------------
// K4: edge kernel — fp16 m16n8k16 + ldmatrix.  256 threads/CTA, 2 CTAs/SM.
// NO full-CTA barriers in the item loop: each warp-pair is independent
// (ti via direct LDG, mpre via per-pair global slab, pair-local sEp/sE/X).
// ---------------------------------------------------------------------------
__global__ void __launch_bounds__(256, 2)
k_edge(const float* __restrict__ be2,
       const float* __restrict__ Winf,
       const float* __restrict__ binf,
       const float* __restrict__ We1,
       const float* __restrict__ We2,
       const float* __restrict__ coords,
       int nitems)
{
    extern __shared__ char smraw[];
    __half* sWt  = (__half*)smraw;                  // 34816 B  [c][k]
    __half* sXh  = (__half*)(smraw + 34816);        // 34816 B  [jl][k]
    float* sCall = (float*)(smraw + 69632);         // 24576 B  all-batch coords
    float* sEp = sCall + BB*3*RR;                   // 128
    float* sE  = sEp + JH;                          // 128
    float* sWd = sE  + JH;                          // 128
    float* sBc = sWd + DD;                          // 128
    float* sWc = sBc + DD;                          // 128

    const int t    = threadIdx.x;
    const int w    = t >> 5;
    const int lane = t & 31;
    const int g    = lane >> 2;
    const int tig  = lane & 3;
    const int pair = w >> 1;            // 0..3
    const int jbase = pair * 32;        // local j
    const int cbase = (w & 1) * 64;
    const int barid = 1 + pair;

    // one-time staging
    for (int idx = t; idx < DD*DD; idx += 256) {
        int k = idx >> 7, c = idx & 127;
        sWt[c*SWH + k] = __float2half_rn(We2[idx]);
    }
    for (int idx = t; idx < BB*RR; idx += 256) {
        int b = idx >> 8, j = idx & 255;
        const float* cp = coords + (size_t)idx*3;
        sCall[b*768 + j]        = cp[0];
        sCall[b*768 + 256 + j]  = cp[1];
        sCall[b*768 + 512 + j]  = cp[2];
    }
    if (t < DD) {
        sWd[t] = We1[2*DD*DD + t];
        sBc[t] = be2[t];
        sWc[t] = Winf[t];
    }
    const float bi = binf[0];
    __syncthreads();

    // ldmatrix per-lane base addresses (fixed across items)
    uint32_t aAddr[2];
    #pragma unroll
    for (int mi = 0; mi < 2; mi++)
        aAddr[mi] = smem_u32(&sXh[(size_t)(jbase + mi*16 + (lane & 15))*SXH
                                  + ((lane >> 4) << 3)]);
    uint32_t bAddr[4];
    #pragma unroll
    for (int nb = 0; nb < 4; nb++)
        bAddr[nb] = smem_u32(&sWt[(size_t)(cbase + nb*16 + ((lane >> 4) << 3) + (lane & 7))*SWH
                                  + (((lane >> 3) & 1) << 3)]);

    const int k4 = lane*4;
    const float wd0 = sWd[k4], wd1 = sWd[k4+1], wd2 = sWd[k4+2], wd3 = sWd[k4+3];
    float bc[16], wc[16];
    #pragma unroll
    for (int ni = 0; ni < 8; ni++)
        #pragma unroll
        for (int q = 0; q < 2; q++) {
            int c = cbase + ni*8 + tig*2 + q;
            bc[ni*2+q] = sBc[c];
            wc[ni*2+q] = sWc[c];
        }

    for (int item = blockIdx.x; item < nitems; item += gridDim.x) {
        const int tile = item >> 1, jhalf = item & 1;
        const int b = tile >> 8, i = tile & 255;
        const int jg0 = jhalf * JH;
        const float* sC = sCall + b*768;

        // per-thread ti load (all warps hit same 4 lines -> L1)
        const float4 tiv = *(const float4*)&g_ti[(size_t)tile*DD + k4];

        // ---- build own 16 local X rows as fp16 ----
        {
            const float* tjb = g_tj + (size_t)b*RR*DD;
            const float cix = sC[i], ciy = sC[256 + i], ciz = sC[512 + i];
            const int jw = jbase + (w & 1)*16;      // local
            #pragma unroll
            for (int jj = 0; jj < 16; jj += 2) {
                const int jl = jw + jj, jl1 = jw + jj + 1;
                const int jA = jg0 + jl, jB = jg0 + jl1;   // global
                float4 tv0 = *(const float4*)&tjb[(size_t)jA*DD + k4];
                float4 tv1 = *(const float4*)&tjb[(size_t)jB*DD + k4];
                float dx0 = sC[jA] - cix, dy0 = sC[256+jA] - ciy, dz0 = sC[512+jA] - ciz;
                float dx1 = sC[jB] - cix, dy1 = sC[256+jB] - ciy, dz1 = sC[512+jB] - ciz;
                float d20 = dx0*dx0 + dy0*dy0 + dz0*dz0;
                float d21 = dx1*dx1 + dy1*dy1 + dz1*dz1;
                __half2 h01 = __floats2half2_rn(lrelu(tiv.x + tv0.x + d20*wd0),
                                                lrelu(tiv.y + tv0.y + d20*wd1));
                __half2 h23 = __floats2half2_rn(lrelu(tiv.z + tv0.z + d20*wd2),
                                                lrelu(tiv.w + tv0.w + d20*wd3));
                uint2 u0; u0.x = *(uint32_t*)&h01; u0.y = *(uint32_t*)&h23;
                *(uint2*)&sXh[(size_t)jl*SXH + k4] = u0;
                __half2 h45 = __floats2half2_rn(lrelu(tiv.x + tv1.x + d21*wd0),
                                                lrelu(tiv.y + tv1.y + d21*wd1));
                __half2 h67 = __floats2half2_rn(lrelu(tiv.z + tv1.z + d21*wd2),
                                                lrelu(tiv.w + tv1.w + d21*wd3));
                uint2 u1; u1.x = *(uint32_t*)&h45; u1.y = *(uint32_t*)&h67;
                *(uint2*)&sXh[(size_t)jl1*SXH + k4] = u1;
            }
        }
        if ((w & 1) == 0) sEp[jbase + lane] = 0.f;
        pair_bar(barid);

        // ---- mainloop: 32x64 warp tile, ldmatrix + m16n8k16 fp16 ----
        float acc[2][8][4];
        #pragma unroll
        for (int mi = 0; mi < 2; mi++)
            #pragma unroll
            for (int ni = 0; ni < 8; ni++)
                #pragma unroll
                for (int q = 0; q < 4; q++) acc[mi][ni][q] = 0.f;

        #pragma unroll
        for (int k0 = 0; k0 < DD; k0 += 16) {
            const uint32_t kb = k0*2;
            uint32_t A[2][4];
            #pragma unroll
            for (int mi = 0; mi < 2; mi++)
                ldsm_x4(A[mi][0], A[mi][1], A[mi][2], A[mi][3], aAddr[mi] + kb);
            uint32_t Bf[8][2];
            #pragma unroll
            for (int nb = 0; nb < 4; nb++)
                ldsm_x4(Bf[nb*2][0], Bf[nb*2][1], Bf[nb*2+1][0], Bf[nb*2+1][1],
                        bAddr[nb] + kb);
            #pragma unroll
            for (int mi = 0; mi < 2; mi++)
                #pragma unroll
                for (int ni = 0; ni < 8; ni++)
                    asm volatile(
                        "mma.sync.aligned.m16n8k16.row.col.f32.f16.f16.f32 "
                        "{%0,%1,%2,%3}, {%4,%5,%6,%7}, {%8,%9}, {%0,%1,%2,%3};"
                        : "+f"(acc[mi][ni][0]), "+f"(acc[mi][ni][1]),
                          "+f"(acc[mi][ni][2]), "+f"(acc[mi][ni][3])
                        : "r"(A[mi][0]), "r"(A[mi][1]), "r"(A[mi][2]), "r"(A[mi][3]),
                          "r"(Bf[ni][0]), "r"(Bf[ni][1]));
        }

        // ---- epilogue: m in place, gate, masked j-reduction ----
        #pragma unroll
        for (int mi = 0; mi < 2; mi++)
            #pragma unroll
            for (int ni = 0; ni < 8; ni++)
                #pragma unroll
                for (int q4 = 0; q4 < 4; q4++)
                    acc[mi][ni][q4] = lrelu(acc[mi][ni][q4] + bc[ni*2 + (q4 & 1)]);

        // pass 1: per-j gate logit partials
        #pragma unroll
        for (int mi = 0; mi < 2; mi++)
            #pragma unroll
            for (int r = 0; r < 2; r++) {
                float p = 0.f;
                #pragma unroll
                for (int ni = 0; ni < 8; ni++)
                    #pragma unroll
                    for (int q = 0; q < 2; q++)
                        p += acc[mi][ni][r*2+q] * wc[ni*2+q];
                p += __shfl_xor_sync(0xffffffffu, p, 1);
                p += __shfl_xor_sync(0xffffffffu, p, 2);
                if (tig == 0) atomicAdd(&sEp[jbase + mi*16 + g + r*8], p);
            }
        pair_bar(barid);
        if ((w & 1) == 0) {
            int jl = jbase + lane;
            float s = sEp[jl] + bi;
            sE[jl] = ((jg0 + jl) == i) ? 0.f : __fdividef(1.f, 1.f + __expf(-s));
        }
        pair_bar(barid);

        // pass 2: mpre[c] = sum_j m*e  (warp's 32 j's) -> per-pair slab (STG)
        float macc[16];
        #pragma unroll
        for (int q = 0; q < 16; q++) macc[q] = 0.f;
        #pragma unroll
        for (int mi = 0; mi < 2; mi++)
            #pragma unroll
            for (int r = 0; r < 2; r++) {
                float e = sE[jbase + mi*16 + g + r*8];
                #pragma unroll
                for (int ni = 0; ni < 8; ni++)
                    #pragma unroll
                    for (int q = 0; q < 2; q++)
                        macc[ni*2+q] += acc[mi][ni][r*2+q] * e;
            }
        #pragma unroll
        for (int q = 0; q < 16; q++) {
            macc[q] += __shfl_xor_sync(0xffffffffu, macc[q], 4);
            macc[q] += __shfl_xor_sync(0xffffffffu, macc[q], 8);
            macc[q] += __shfl_xor_sync(0xffffffffu, macc[q], 16);
        }
        if (g == 0) {
            float* slab = g_mp8 + ((size_t)(pair*2 + jhalf)*NROW + tile)*DD;
            #pragma unroll
            for (int q = 0; q < 16; q++)
                slab[cbase + (q >> 1)*8 + tig*2 + (q & 1)] = macc[q];
        }
    }
}

// ---------------------------------------------------------------------------
extern "C" void kernel_launch(void* const* d_in, const int* in_sizes, int n_in,
                              void* d_out, int out_size)
{
    const float* fres   = (const float*)d_in[0];
    const float* coords = (const float*)d_in[1];
    const float* Wemb   = (const float*)d_in[2];
    const float* We1    = (const float*)d_in[3];
    const float* be1    = (const float*)d_in[4];
    const float* We2    = (const float*)d_in[5];
    const float* be2    = (const float*)d_in[6];
    const float* Winf   = (const float*)d_in[7];
    const float* binf   = (const float*)d_in[8];
    const float* Wh1    = (const float*)d_in[9];
    const float* bh1    = (const float*)d_in[10];
    const float* Wh2    = (const float*)d_in[11];
    const float* bh2    = (const float*)d_in[12];
    float* out = (float*)d_out;

    const int EDGE_SMEM = 69632 + (BB*3*RR + 2*JH + 3*DD)*(int)sizeof(float);  // 96768
    cudaFuncSetAttribute(k_edge, cudaFuncAttributeMaxDynamicSharedMemorySize, EDGE_SMEM);

    k_embed_titj<<<NROW/8, 256>>>(fres, Wemb, We1, be1);
    k_edge<<<296, 256, EDGE_SMEM>>>(be2, Winf, binf, We1, We2, coords, NROW*2);
    k_node_titj<<<NROW/8, 256>>>(Wh1, bh1, Wh2, bh2, We1, be1);
    k_edge<<<296, 256, EDGE_SMEM>>>(be2, Winf, binf, We1, We2, coords, NROW*2);
    k_node_out<<<NROW/8, 256>>>(Wh1, bh1, Wh2, bh2, out);
}